// round 12
// baseline (speedup 1.0000x reference)
#include <cuda_runtime.h>
#include <cuda_bf16.h>

// BilateralGridCP4D fused eval.
// Round-12: back to R10's proven ITER=4 pipeline (32 regs / 85% occ; ITER=8
// cost 15 regs and 33% occupancy), keep streaming cache hints, and remove all
// loop bounds checks via an exact-divisibility dispatch (N=2^22 % 1024 == 0).

#define RANK 5
#define THREADS 256
#define ITER 4

// layout: [0..59] fac0 native (12,5) row-major, [60..83] w1 (8,3),
//         [84..91] b1, [92..99] w2, [100] b2
__constant__ float c_params[104];
__device__   float g_staging[104];

__global__ void setup_kernel(const float* __restrict__ fac0,
                             const float* __restrict__ w1,
                             const float* __restrict__ b1,
                             const float* __restrict__ w2,
                             const float* __restrict__ b2)
{
    int t = threadIdx.x;
    if (t < 60)        g_staging[t] = fac0[t];
    else if (t < 84)   g_staging[t] = w1[t - 60];
    else if (t < 92)   g_staging[t] = b1[t - 84];
    else if (t < 100)  g_staging[t] = w2[t - 92];
    else if (t == 100) g_staging[100] = b2[0];
}

// pt[i*RANK + r] = (f0, f1-f0); val = f0 + w*delta. pos pre-clamped.
__device__ __forceinline__ void interp_mul_pt(const float2* __restrict__ pt,
                                              float pos, float coef[RANK], bool first)
{
    int i0 = (int)pos;
    float w = pos - (float)i0;
    const float2* p = pt + i0 * RANK;
#pragma unroll
    for (int r = 0; r < RANK; r++) {
        float2 f = p[r];
        float val = fmaf(w, f.y, f.x);
        if (first) coef[r] = val;
        else       coef[r] *= val;
    }
}

__device__ __forceinline__ void build_tables(float2* s_t1, float2* s_t2,
                                             float2* s_t3, float2* s_t4,
                                             const float* fac1, const float* fac2,
                                             const float* fac3, const float* fac4,
                                             int tid)
{
    if (tid < 35) {
        int i = tid / RANK, r = tid % RANK;
        float a = fac1[r * 8 + i], b = fac1[r * 8 + i + 1];
        s_t1[tid] = make_float2(a, b - a);
    }
    if (tid < 75) {
        int i = tid / RANK, r = tid % RANK;
        float a = fac2[r * 16 + i], b = fac2[r * 16 + i + 1];
        s_t2[tid] = make_float2(a, b - a);
    } else if (tid < 150) {
        int k = tid - 75, i = k / RANK, r = k % RANK;
        float a = fac3[r * 16 + i], b = fac3[r * 16 + i + 1];
        s_t3[k] = make_float2(a, b - a);
    } else if (tid < 225) {
        int k = tid - 150, i = k / RANK, r = k % RANK;
        float a = fac4[r * 16 + i], b = fac4[r * 16 + i + 1];
        s_t4[k] = make_float2(a, b - a);
    }
}

// One point's full evaluation: inputs -> 3 float4 stores.
__device__ __forceinline__ void eval_point(float x, float y, float z,
                                           float r0, float g0, float b0,
                                           const float2* s_t1, const float2* s_t2,
                                           const float2* s_t3, const float2* s_t4,
                                           float4* __restrict__ out4, int i)
{
    // ---- rgb -> gray MLP (scalar constant reads -> LDCU uniform path) ----
    float acc = c_params[100];
#pragma unroll
    for (int h = 0; h < 8; h++) {
        float hv = fmaf(c_params[60 + h * 3 + 0], r0,
                   fmaf(c_params[60 + h * 3 + 1], g0,
                   fmaf(c_params[60 + h * 3 + 2], b0, c_params[84 + h])));
        hv = fmaxf(hv, 0.0f);
        acc = fmaf(c_params[92 + h], hv, acc);
    }
    // gray = tanh(2*acc) = 1 - t, t = 2/(exp(4*acc)+1)
    float e = __expf(4.0f * acc);
    float t = __fdividef(2.0f, e + 1.0f);

    // ---- positions (pos = v*0.25*(D-1) + 0.5*(D-1), BOUND=2) ----
    const float HI8  = 6.9999995f;
    const float HI16 = 14.999999f;
    float p1 = fminf(fmaxf(fmaf(x, 1.75f, 3.5f), 0.0f), HI8);
    float p2 = fminf(fmaxf(fmaf(y, 3.75f, 7.5f), 0.0f), HI16);
    float p3 = fminf(fmaxf(fmaf(z, 3.75f, 7.5f), 0.0f), HI16);
    float p4 = fminf(fmaf(-7.5f, t, 15.0f), HI16);   // gray axis, pos >= 0

    float coef[RANK];
    interp_mul_pt(s_t1, p1, coef, true);
    interp_mul_pt(s_t2, p2, coef, false);
    interp_mul_pt(s_t3, p3, coef, false);
    interp_mul_pt(s_t4, p4, coef, false);

    // ---- 5 -> 12 linear, fac0 native (12,5), scalar LDCU reads ----
    float4 o[3];
#pragma unroll
    for (int q = 0; q < 3; q++) {
        o[q].x = coef[0] * c_params[(4 * q + 0) * RANK];
        o[q].y = coef[0] * c_params[(4 * q + 1) * RANK];
        o[q].z = coef[0] * c_params[(4 * q + 2) * RANK];
        o[q].w = coef[0] * c_params[(4 * q + 3) * RANK];
    }
#pragma unroll
    for (int r = 1; r < RANK; r++) {
#pragma unroll
        for (int q = 0; q < 3; q++) {
            o[q].x = fmaf(coef[r], c_params[(4 * q + 0) * RANK + r], o[q].x);
            o[q].y = fmaf(coef[r], c_params[(4 * q + 1) * RANK + r], o[q].y);
            o[q].z = fmaf(coef[r], c_params[(4 * q + 2) * RANK + r], o[q].z);
            o[q].w = fmaf(coef[r], c_params[(4 * q + 3) * RANK + r], o[q].w);
        }
    }

    int base = 3 * i;
    __stcs(&out4[base + 0], o[0]);
    __stcs(&out4[base + 1], o[1]);
    __stcs(&out4[base + 2], o[2]);
}

// EXACT=true: npts == gridDim.x * THREADS * ITER, no bounds checks anywhere.
template <bool EXACT>
__global__ __launch_bounds__(THREADS)
void bgrid_cp4d_kernel(const float* __restrict__ xyz,
                       const float* __restrict__ rgb,
                       const float* __restrict__ fac1,
                       const float* __restrict__ fac2,
                       const float* __restrict__ fac3,
                       const float* __restrict__ fac4,
                       float4* __restrict__ out4,
                       int npts)
{
    __shared__ float2 s_t1[7 * RANK];
    __shared__ float2 s_t2[15 * RANK];
    __shared__ float2 s_t3[15 * RANK];
    __shared__ float2 s_t4[15 * RANK];

    int tid = threadIdx.x;
    build_tables(s_t1, s_t2, s_t3, s_t4, fac1, fac2, fac3, fac4, tid);
    __syncthreads();

    const int stride = gridDim.x * THREADS;
    int i = blockIdx.x * THREADS + tid;
    if (!EXACT && i >= npts) return;

    float x  = __ldcs(&xyz[3 * i + 0]);
    float y  = __ldcs(&xyz[3 * i + 1]);
    float z  = __ldcs(&xyz[3 * i + 2]);
    float r0 = __ldcs(&rgb[3 * i + 0]);
    float g0 = __ldcs(&rgb[3 * i + 1]);
    float b0 = __ldcs(&rgb[3 * i + 2]);

#pragma unroll
    for (int k = 0; k < ITER; k++) {
        float xn, yn, zn, rn, gn, bn;
        int inext = i + stride;
        if (k + 1 < ITER) {
            int ip = EXACT ? inext : ((inext < npts) ? inext : i);
            xn = __ldcs(&xyz[3 * ip + 0]);
            yn = __ldcs(&xyz[3 * ip + 1]);
            zn = __ldcs(&xyz[3 * ip + 2]);
            rn = __ldcs(&rgb[3 * ip + 0]);
            gn = __ldcs(&rgb[3 * ip + 1]);
            bn = __ldcs(&rgb[3 * ip + 2]);
        }

        eval_point(x, y, z, r0, g0, b0, s_t1, s_t2, s_t3, s_t4, out4, i);

        if (k + 1 < ITER) {
            if (!EXACT && inext >= npts) return;
            i = inext;
            x = xn; y = yn; z = zn;
            r0 = rn; g0 = gn; b0 = bn;
        }
    }
}

extern "C" void kernel_launch(void* const* d_in, const int* in_sizes, int n_in,
                              void* d_out, int out_size)
{
    const float* xyz  = (const float*)d_in[0];
    const float* rgb  = (const float*)d_in[1];
    const float* fac1 = (const float*)d_in[3];
    const float* fac2 = (const float*)d_in[4];
    const float* fac3 = (const float*)d_in[5];
    const float* fac4 = (const float*)d_in[6];
    float4* out4 = (float4*)d_out;

    // Gather uniform params (one kernel node) then one memcpy into constant.
    setup_kernel<<<1, 128>>>((const float*)d_in[2], (const float*)d_in[7],
                             (const float*)d_in[8], (const float*)d_in[9],
                             (const float*)d_in[10]);
    void* staging_ptr = nullptr;
    cudaGetSymbolAddress(&staging_ptr, g_staging);
    cudaMemcpyToSymbolAsync(c_params, staging_ptr, 101 * sizeof(float), 0,
                            cudaMemcpyDeviceToDevice, 0);

    int npts = in_sizes[0] / 3;
    int per_block = THREADS * ITER;
    if (npts % per_block == 0) {
        int blocks = npts / per_block;
        bgrid_cp4d_kernel<true><<<blocks, THREADS>>>(xyz, rgb, fac1, fac2, fac3,
                                                     fac4, out4, npts);
    } else {
        int blocks = (npts + per_block - 1) / per_block;
        bgrid_cp4d_kernel<false><<<blocks, THREADS>>>(xyz, rgb, fac1, fac2, fac3,
                                                      fac4, out4, npts);
    }
}

// round 13
// speedup vs baseline: 1.1469x; 1.1469x over previous
#include <cuda_runtime.h>
#include <cuda_bf16.h>

// BilateralGridCP4D fused eval.
// Round-13: R10's champion config byte-for-byte (ITER=4, guarded pipeline
// rotation -- the guards double as code-motion barriers keeping regs at 32;
// removing them in R12 exploded regs to 64 / occ to 42%). Single isolated
// change vs R10: streaming cache hints __ldcs/__stcs (pure policy metadata).

#define RANK 5
#define THREADS 256
#define ITER 4

// layout: [0..59] fac0 native (12,5) row-major, [60..83] w1 (8,3),
//         [84..91] b1, [92..99] w2, [100] b2
__constant__ float c_params[104];
__device__   float g_staging[104];

__global__ void setup_kernel(const float* __restrict__ fac0,
                             const float* __restrict__ w1,
                             const float* __restrict__ b1,
                             const float* __restrict__ w2,
                             const float* __restrict__ b2)
{
    int t = threadIdx.x;
    if (t < 60)        g_staging[t] = fac0[t];
    else if (t < 84)   g_staging[t] = w1[t - 60];
    else if (t < 92)   g_staging[t] = b1[t - 84];
    else if (t < 100)  g_staging[t] = w2[t - 92];
    else if (t == 100) g_staging[100] = b2[0];
}

// pt[i*RANK + r] = (f0, f1-f0); val = f0 + w*delta. pos pre-clamped.
__device__ __forceinline__ void interp_mul_pt(const float2* __restrict__ pt,
                                              float pos, float coef[RANK], bool first)
{
    int i0 = (int)pos;
    float w = pos - (float)i0;
    const float2* p = pt + i0 * RANK;
#pragma unroll
    for (int r = 0; r < RANK; r++) {
        float2 f = p[r];
        float val = fmaf(w, f.y, f.x);
        if (first) coef[r] = val;
        else       coef[r] *= val;
    }
}

__global__ __launch_bounds__(THREADS)
void bgrid_cp4d_kernel(const float* __restrict__ xyz,
                       const float* __restrict__ rgb,
                       const float* __restrict__ fac1,  // (5,8)
                       const float* __restrict__ fac2,  // (5,16)
                       const float* __restrict__ fac3,  // (5,16)
                       const float* __restrict__ fac4,  // (5,16)
                       float4* __restrict__ out4,       // N*3 float4
                       int npts)
{
    __shared__ float2 s_t1[7 * RANK];    // D=8
    __shared__ float2 s_t2[15 * RANK];   // D=16
    __shared__ float2 s_t3[15 * RANK];
    __shared__ float2 s_t4[15 * RANK];

    int tid = threadIdx.x;
    if (tid < 35) {
        int i = tid / RANK, r = tid % RANK;
        float a = fac1[r * 8 + i], b = fac1[r * 8 + i + 1];
        s_t1[tid] = make_float2(a, b - a);
    }
    if (tid < 75) {
        int i = tid / RANK, r = tid % RANK;
        float a = fac2[r * 16 + i], b = fac2[r * 16 + i + 1];
        s_t2[tid] = make_float2(a, b - a);
    } else if (tid < 150) {
        int k = tid - 75, i = k / RANK, r = k % RANK;
        float a = fac3[r * 16 + i], b = fac3[r * 16 + i + 1];
        s_t3[k] = make_float2(a, b - a);
    } else if (tid < 225) {
        int k = tid - 150, i = k / RANK, r = k % RANK;
        float a = fac4[r * 16 + i], b = fac4[r * 16 + i + 1];
        s_t4[k] = make_float2(a, b - a);
    }
    __syncthreads();

    const int stride = gridDim.x * THREADS;
    int i = blockIdx.x * THREADS + tid;
    if (i >= npts) return;

    // prologue: load inputs for first point (streaming: touched once)
    float x  = __ldcs(&xyz[3 * i + 0]);
    float y  = __ldcs(&xyz[3 * i + 1]);
    float z  = __ldcs(&xyz[3 * i + 2]);
    float r0 = __ldcs(&rgb[3 * i + 0]);
    float g0 = __ldcs(&rgb[3 * i + 1]);
    float b0 = __ldcs(&rgb[3 * i + 2]);

#pragma unroll
    for (int k = 0; k < ITER; k++) {
        // ---- prefetch next iteration's inputs ----
        float xn, yn, zn, rn, gn, bn;
        int inext = i + stride;
        if (k + 1 < ITER) {
            int ip = (inext < npts) ? inext : i;   // safe addr, discarded if OOB
            xn = __ldcs(&xyz[3 * ip + 0]);
            yn = __ldcs(&xyz[3 * ip + 1]);
            zn = __ldcs(&xyz[3 * ip + 2]);
            rn = __ldcs(&rgb[3 * ip + 0]);
            gn = __ldcs(&rgb[3 * ip + 1]);
            bn = __ldcs(&rgb[3 * ip + 2]);
        }

        // ---- rgb -> gray MLP (scalar constant reads -> LDCU uniform path) ----
        float acc = c_params[100];
#pragma unroll
        for (int h = 0; h < 8; h++) {
            float hv = fmaf(c_params[60 + h * 3 + 0], r0,
                       fmaf(c_params[60 + h * 3 + 1], g0,
                       fmaf(c_params[60 + h * 3 + 2], b0, c_params[84 + h])));
            hv = fmaxf(hv, 0.0f);
            acc = fmaf(c_params[92 + h], hv, acc);
        }
        // gray = tanh(2*acc) = 1 - t, t = 2/(exp(4*acc)+1)
        float e = __expf(4.0f * acc);
        float t = __fdividef(2.0f, e + 1.0f);

        // ---- positions (pos = v*0.25*(D-1) + 0.5*(D-1), BOUND=2) ----
        const float HI8  = 6.9999995f;
        const float HI16 = 14.999999f;
        float p1 = fminf(fmaxf(fmaf(x, 1.75f, 3.5f), 0.0f), HI8);
        float p2 = fminf(fmaxf(fmaf(y, 3.75f, 7.5f), 0.0f), HI16);
        float p3 = fminf(fmaxf(fmaf(z, 3.75f, 7.5f), 0.0f), HI16);
        float p4 = fminf(fmaf(-7.5f, t, 15.0f), HI16);  // gray axis, pos >= 0

        float coef[RANK];
        interp_mul_pt(s_t1, p1, coef, true);
        interp_mul_pt(s_t2, p2, coef, false);
        interp_mul_pt(s_t3, p3, coef, false);
        interp_mul_pt(s_t4, p4, coef, false);

        // ---- 5 -> 12 linear, fac0 native (12,5), scalar LDCU reads ----
        float4 o[3];
#pragma unroll
        for (int q = 0; q < 3; q++) {
            o[q].x = coef[0] * c_params[(4 * q + 0) * RANK];
            o[q].y = coef[0] * c_params[(4 * q + 1) * RANK];
            o[q].z = coef[0] * c_params[(4 * q + 2) * RANK];
            o[q].w = coef[0] * c_params[(4 * q + 3) * RANK];
        }
#pragma unroll
        for (int r = 1; r < RANK; r++) {
#pragma unroll
            for (int q = 0; q < 3; q++) {
                o[q].x = fmaf(coef[r], c_params[(4 * q + 0) * RANK + r], o[q].x);
                o[q].y = fmaf(coef[r], c_params[(4 * q + 1) * RANK + r], o[q].y);
                o[q].z = fmaf(coef[r], c_params[(4 * q + 2) * RANK + r], o[q].z);
                o[q].w = fmaf(coef[r], c_params[(4 * q + 3) * RANK + r], o[q].w);
            }
        }

        int base = 3 * i;
        __stcs(&out4[base + 0], o[0]);
        __stcs(&out4[base + 1], o[1]);
        __stcs(&out4[base + 2], o[2]);

        // ---- rotate pipeline (guards double as code-motion barriers) ----
        if (k + 1 < ITER) {
            if (inext >= npts) return;
            i = inext;
            x = xn; y = yn; z = zn;
            r0 = rn; g0 = gn; b0 = bn;
        }
    }
}

extern "C" void kernel_launch(void* const* d_in, const int* in_sizes, int n_in,
                              void* d_out, int out_size)
{
    const float* xyz  = (const float*)d_in[0];
    const float* rgb  = (const float*)d_in[1];
    const float* fac1 = (const float*)d_in[3];
    const float* fac2 = (const float*)d_in[4];
    const float* fac3 = (const float*)d_in[5];
    const float* fac4 = (const float*)d_in[6];
    float4* out4 = (float4*)d_out;

    // Gather uniform params (one kernel node) then one memcpy into constant.
    setup_kernel<<<1, 128>>>((const float*)d_in[2], (const float*)d_in[7],
                             (const float*)d_in[8], (const float*)d_in[9],
                             (const float*)d_in[10]);
    void* staging_ptr = nullptr;
    cudaGetSymbolAddress(&staging_ptr, g_staging);
    cudaMemcpyToSymbolAsync(c_params, staging_ptr, 101 * sizeof(float), 0,
                            cudaMemcpyDeviceToDevice, 0);

    int npts = in_sizes[0] / 3;
    int per_block = THREADS * ITER;
    int blocks = (npts + per_block - 1) / per_block;
    bgrid_cp4d_kernel<<<blocks, THREADS>>>(xyz, rgb, fac1, fac2, fac3, fac4,
                                           out4, npts);
}